// round 16
// baseline (speedup 1.0000x reference)
#include <cuda_runtime.h>
#include <cstdint>
#include <math.h>

#define BB 2048
#define LL 50
#define FF 64
#define HH 128
#define NOUTS 3
#define G4 512   // 4*H
#define KENC 192 // F + H
#define KDEC 384 // 2H + H
#define BME 16   // rows per encoder block

// ---------------- scratch (static device allocations only) ----------------
__device__ float g_hde[BB*HH];
__device__ float g_cde[BB*HH];
__device__ float g_enc[BB*LL*HH];
__device__ float g_ctx[BB*HH];
__device__ float g_hproj[BB*HH];
__device__ float g_e2[BB*LL];
// encoder packed weights (full width): [k][nc*4 + gate], n = gate*128 + nc
__device__ float g_WencF[KENC*G4];
__device__ float g_bencF[G4];
// decoder packed weights (halved): [half][k][nl*4 + gate], n = gate*128 + half*64 + nl
__device__ float g_WdecP[2*KDEC*256];
__device__ float g_bdecP[512];
// h-side decoder attention weight, transposed: [step][c][k]
__device__ float g_W2T[NOUTS*128*128];

__device__ __forceinline__ float sigf(float v){ return 1.f/(1.f+__expf(-v)); }

__device__ __forceinline__ void cp16(void* dst, const void* src){
    unsigned int d = (unsigned int)__cvta_generic_to_shared(dst);
    asm volatile("cp.async.ca.shared.global [%0], [%1], 16;" :: "r"(d), "l"(src));
}
__device__ __forceinline__ void cp_commit(){ asm volatile("cp.async.commit_group;"); }
__device__ __forceinline__ void cp_wait1(){ asm volatile("cp.async.wait_group 1;"); }
__device__ __forceinline__ void cp_wait0(){ asm volatile("cp.async.wait_group 0;"); }

// ---------------- init / weight prep ----------------
__global__ void zero_kernel(){
    int idx = blockIdx.x*256 + threadIdx.x;
    if (idx < BB*HH){ g_hde[idx]=0.f; g_cde[idx]=0.f; }
}

__global__ void prep_kernel(const float* __restrict__ eWih, const float* __restrict__ eWhh,
                            const float* __restrict__ ebih, const float* __restrict__ ebhh,
                            const float* __restrict__ dWih, const float* __restrict__ dWhh,
                            const float* __restrict__ dbih, const float* __restrict__ dbhh,
                            const float* __restrict__ ddw){
    int idx = blockIdx.x*256 + threadIdx.x;
    if (idx < KENC*G4){
        int k = idx >> 9, c = idx & 511;
        int nc = c >> 2, g = c & 3;
        int n = g*128 + nc;
        g_WencF[idx] = (k < FF) ? eWih[n*FF + k] : eWhh[n*HH + (k - FF)];
    }
    if (idx < 2*KDEC*256){
        int half = idx / (KDEC*256);
        int rem  = idx % (KDEC*256);
        int k = rem >> 8, r = rem & 255;
        int nl = r >> 2, g = r & 3;
        int n = g*128 + half*64 + nl;
        g_WdecP[idx] = (k < 256) ? dWih[n*256 + k] : dWhh[n*HH + (k - 256)];
    }
    if (idx < NOUTS*128*128){
        int s = idx / (128*128);
        int rem = idx % (128*128);
        int c = rem >> 7, k = rem & 127;
        g_W2T[idx] = ddw[s*256*128 + (128 + k)*128 + c];
    }
    if (idx < 512){
        int nc = idx >> 2, g = idx & 3;
        int n = g*128 + nc;
        g_bencF[idx] = ebih[n] + ebhh[n];
        int half = idx >> 8, r = idx & 255;
        int nl2 = r >> 2, g2 = r & 3;
        int n2 = g2*128 + half*64 + nl2;
        g_bdecP[idx] = dbih[n2] + dbhh[n2];
    }
}

// =======================================================================
// PERSISTENT ENCODER v3 (unchanged from best): grid 128, 512 threads.
// =======================================================================
__global__ void enc_persist_kernel(const float* __restrict__ x,
                                   const float* __restrict__ aw,
                                   const float* __restrict__ ab){
    extern __shared__ float sm[];
    float* sAT = sm;             // [k][m] stride 16; k<64: xin, k>=64: h
    float* sE  = sm + 3072;      // [2][16][64]
    float* sC  = sm + 5120;      // [16][128]
    float* sAW = sm + 7168;      // aw[t]: 192x64
    float* sB  = sm + 19456;     // 2 x 32x512 weight slabs
    int tid = threadIdx.x;
    int row0 = blockIdx.x * BME;
    int tx = tid & 127, ty = tid >> 7;
    int cg = tid & 15, r1 = (tid >> 4) & 15, ks = tid >> 8;

    for (int i = tid; i < 2048; i += 512) sAT[1024 + i] = 0.f;
    for (int i = tid; i < 2048; i += 512) sC[i] = 0.f;
    float4 bg = *(const float4*)&g_bencF[tx*4];
    for (int i = tid*4; i < KENC*FF; i += 2048) cp16(sAW + i, aw + i);
    cp_commit(); cp_wait0();
    __syncthreads();

    for (int t = 0; t < LL; t++){
        for (int i = tid; i < BME*64; i += 512){
            int m = i >> 6, f = i & 63;
            sAT[f*16 + m] = x[((row0+m)*LL + t)*FF + f];
        }
        __syncthreads();

        {
            float a0=0.f, a1=0.f, a2=0.f, a3=0.f;
            int kbeg = ks*96;
            #pragma unroll 8
            for (int k = kbeg; k < kbeg+96; k++){
                float4 b = *(const float4*)&sAW[k*64 + cg*4];
                float a = sAT[k*16 + r1];
                a0 += a*b.x; a1 += a*b.y; a2 += a*b.z; a3 += a*b.w;
            }
            *(float4*)&sE[(ks*16 + r1)*64 + cg*4] = make_float4(a0, a1, a2, a3);
        }
        __syncthreads();

        {
            int w = tid >> 5, lane = tid & 31;
            float b0 = __ldg(&ab[t*FF + lane]);
            float b1 = __ldg(&ab[t*FF + 32 + lane]);
            float v0 = tanhf(sE[w*64 + lane]        + sE[(16+w)*64 + lane]        + b0);
            float v1 = tanhf(sE[w*64 + lane + 32]   + sE[(16+w)*64 + lane + 32]   + b1);
            float mx = fmaxf(v0, v1);
            #pragma unroll
            for (int off = 16; off; off >>= 1) mx = fmaxf(mx, __shfl_xor_sync(0xffffffffu, mx, off));
            float e0 = __expf(v0 - mx), e1 = __expf(v1 - mx);
            float s = e0 + e1;
            #pragma unroll
            for (int off = 16; off; off >>= 1) s += __shfl_xor_sync(0xffffffffu, s, off);
            float inv = 1.f/s;
            sAT[lane*16 + w]      *= e0*inv;
            sAT[(lane+32)*16 + w] *= e1*inv;
        }
        __syncthreads();

        if (t+1 < LL){
            const float* awn = aw + (size_t)(t+1)*KENC*FF;
            for (int i = tid*4; i < KENC*FF; i += 2048) cp16(sAW + i, awn + i);
        }
        for (int i = tid*4; i < 16384; i += 2048) cp16(sB + i, g_WencF + i);
        cp_commit();
        float acc[4][4] = {};
        #pragma unroll 1
        for (int s = 0; s < 6; s++){
            if (s < 5){
                float* dst = sB + ((s+1)&1)*16384;
                const float* src = g_WencF + (s+1)*16384;
                for (int i = tid*4; i < 16384; i += 2048) cp16(dst + i, src + i);
                cp_commit(); cp_wait1();
            } else cp_wait0();
            __syncthreads();
            const float* Bf = sB + (s&1)*16384;
            #pragma unroll
            for (int kk = 0; kk < 32; kk++){
                int k = s*32 + kk;
                float4 a = *(const float4*)&sAT[k*16 + ty*4];
                float4 b = *(const float4*)&Bf[kk*512 + tx*4];
                acc[0][0]+=a.x*b.x; acc[0][1]+=a.x*b.y; acc[0][2]+=a.x*b.z; acc[0][3]+=a.x*b.w;
                acc[1][0]+=a.y*b.x; acc[1][1]+=a.y*b.y; acc[1][2]+=a.y*b.z; acc[1][3]+=a.y*b.w;
                acc[2][0]+=a.z*b.x; acc[2][1]+=a.z*b.y; acc[2][2]+=a.z*b.z; acc[2][3]+=a.z*b.w;
                acc[3][0]+=a.w*b.x; acc[3][1]+=a.w*b.y; acc[3][2]+=a.w*b.z; acc[3][3]+=a.w*b.w;
            }
            __syncthreads();
        }
        #pragma unroll
        for (int q = 0; q < 4; q++){
            int ml = ty*4 + q;
            float ig = sigf (acc[q][0] + bg.x);
            float fg = sigf (acc[q][1] + bg.y);
            float gg = tanhf(acc[q][2] + bg.z);
            float og = sigf (acc[q][3] + bg.w);
            float cn = fg*sC[ml*128 + tx] + ig*gg;
            sC[ml*128 + tx] = cn;
            float h = og*tanhf(cn);
            sAT[(64+tx)*16 + ml] = h;
            g_enc[((row0+ml)*LL + t)*HH + tx] = h;
        }
    }
}

// =======================================================================
// FUSED DECODER LSTM STEP: grid (2, 128), BK=32 cp.async pipeline, K=384
// =======================================================================
__global__ void dec_step_kernel(){
    extern __shared__ float sm[];
    float* sAT = sm;                  // 384*20 = 7680
    float* sB  = sm + 7680;           // 2 x 32x256 = 16384
    int tid = threadIdx.x;
    int half = blockIdx.x;
    int row0 = blockIdx.y * 16;

    for (int i = tid; i < 16*128; i += 256){
        int m = i >> 7, k = i & 127;
        float ctx = g_ctx[(row0+m)*HH + k];
        float h   = g_hde[(row0+m)*HH + k];
        sAT[k*20 + m]       = ctx;
        sAT[(128+k)*20 + m] = h;
        sAT[(256+k)*20 + m] = h;
    }
    int tx = tid & 63, ty = tid >> 6;
    const float* Wp = g_WdecP + half*(KDEC*256);
    {
        #pragma unroll
        for (int i = tid*4; i < 8192; i += 1024) cp16(sB + i, Wp + i);
        cp_commit();
    }
    __syncthreads();
    float acc[4][4] = {};
    #pragma unroll 1
    for (int s = 0; s < 12; s++){
        if (s < 11){
            float* dst = sB + ((s+1)&1)*8192;
            const float* src = Wp + (s+1)*8192;
            #pragma unroll
            for (int i = tid*4; i < 8192; i += 1024) cp16(dst + i, src + i);
            cp_commit();
            cp_wait1();
        } else {
            cp_wait0();
        }
        __syncthreads();
        const float* Bf = sB + (s&1)*8192;
        #pragma unroll
        for (int kk = 0; kk < 32; kk++){
            int k = s*32 + kk;
            float4 a = *(const float4*)&sAT[k*20 + ty*4];
            float4 b = *(const float4*)&Bf[kk*256 + tx*4];
            acc[0][0]+=a.x*b.x; acc[0][1]+=a.x*b.y; acc[0][2]+=a.x*b.z; acc[0][3]+=a.x*b.w;
            acc[1][0]+=a.y*b.x; acc[1][1]+=a.y*b.y; acc[1][2]+=a.y*b.z; acc[1][3]+=a.y*b.w;
            acc[2][0]+=a.z*b.x; acc[2][1]+=a.z*b.y; acc[2][2]+=a.z*b.z; acc[2][3]+=a.z*b.w;
            acc[3][0]+=a.w*b.x; acc[3][1]+=a.w*b.y; acc[3][2]+=a.w*b.z; acc[3][3]+=a.w*b.w;
        }
        __syncthreads();
    }
    {
        int n = half*64 + tx;
        const float* bP = g_bdecP + half*256;
        float b0 = bP[tx*4+0], b1 = bP[tx*4+1], b2 = bP[tx*4+2], b3 = bP[tx*4+3];
        #pragma unroll
        for (int q = 0; q < 4; q++){
            int row = row0 + ty*4 + q;
            float ig = sigf (acc[q][0] + b0);
            float fg = sigf (acc[q][1] + b1);
            float gg = tanhf(acc[q][2] + b2);
            float og = sigf (acc[q][3] + b3);
            float cn = fg*g_cde[row*HH + n] + ig*gg;
            g_cde[row*HH + n] = cn;
            g_hde[row*HH + n] = og*tanhf(cn);
        }
    }
}

// ---------------- hproj v3: transposed weights, contiguous LDG.128 ----------
__global__ void hproj_kernel(const float* __restrict__ ddb, int step){
    __shared__ float shT[128*16];   // [k][m] stride 16
    int tid = threadIdx.x;
    int row0 = blockIdx.x * 16;
    for (int i = tid; i < 2048; i += 256){
        int m = i >> 7, k = i & 127;
        shT[k*16 + m] = g_hde[(row0+m)*HH + k];
    }
    __syncthreads();
    int c = tid & 127, rg = tid >> 7;    // rows rg*8..rg*8+7
    const float* Wt = g_W2T + step*128*128 + c*128;
    float acc[8] = {};
    #pragma unroll 8
    for (int k = 0; k < 128; k += 4){
        float4 b = *(const float4*)&Wt[k];
        #pragma unroll
        for (int j = 0; j < 4; j++){
            float bj = j==0?b.x : j==1?b.y : j==2?b.z : b.w;
            float4 h0 = *(const float4*)&shT[(k+j)*16 + rg*8];
            float4 h1 = *(const float4*)&shT[(k+j)*16 + rg*8 + 4];
            acc[0]+=h0.x*bj; acc[1]+=h0.y*bj; acc[2]+=h0.z*bj; acc[3]+=h0.w*bj;
            acc[4]+=h1.x*bj; acc[5]+=h1.y*bj; acc[6]+=h1.z*bj; acc[7]+=h1.w*bj;
        }
    }
    float bias = ddb[step*128 + c];
    #pragma unroll
    for (int r = 0; r < 8; r++)
        g_hproj[(row0 + rg*8 + r)*HH + c] = acc[r] + bias;
}

// ---------------- decoder temporal attention: 512 threads, 4x8 micro ----------
__global__ void __launch_bounds__(512, 2)
dattn_kernel(const float* __restrict__ ddw, const float* __restrict__ dlw,
             const float* __restrict__ dlb, int step){
    __shared__ float sA[16*136];
    __shared__ float sB[16*128];
    __shared__ float sdl[128];
    __shared__ float red[128][17];
    int tid = threadIdx.x, tx = tid & 15, ty = tid >> 4;   // ty 0..31
    int row0 = blockIdx.x * 128;
    if (tid < 128) sdl[tid] = dlw[step*128 + tid];
    const float* W = ddw + step*256*128;
    float acc[4][8] = {};
    for (int k0 = 0; k0 < 128; k0 += 16){
        for (int i = tid; i < 2048; i += 512){
            int m = i >> 4, k = i & 15;
            sA[k*136 + m] = g_enc[(row0+m)*HH + k0 + k];
        }
        for (int i = tid; i < 2048; i += 512){
            int k = i >> 7, n = i & 127;
            sB[k*128 + n] = W[(k0+k)*128 + n];
        }
        __syncthreads();
        #pragma unroll
        for (int kk = 0; kk < 16; kk++){
            float4 a = *(const float4*)&sA[kk*136 + ty*4];
            float4 b0 = *(const float4*)&sB[kk*128 + tx*8];
            float4 b1 = *(const float4*)&sB[kk*128 + tx*8 + 4];
            acc[0][0]+=a.x*b0.x; acc[0][1]+=a.x*b0.y; acc[0][2]+=a.x*b0.z; acc[0][3]+=a.x*b0.w;
            acc[0][4]+=a.x*b1.x; acc[0][5]+=a.x*b1.y; acc[0][6]+=a.x*b1.z; acc[0][7]+=a.x*b1.w;
            acc[1][0]+=a.y*b0.x; acc[1][1]+=a.y*b0.y; acc[1][2]+=a.y*b0.z; acc[1][3]+=a.y*b0.w;
            acc[1][4]+=a.y*b1.x; acc[1][5]+=a.y*b1.y; acc[1][6]+=a.y*b1.z; acc[1][7]+=a.y*b1.w;
            acc[2][0]+=a.z*b0.x; acc[2][1]+=a.z*b0.y; acc[2][2]+=a.z*b0.z; acc[2][3]+=a.z*b0.w;
            acc[2][4]+=a.z*b1.x; acc[2][5]+=a.z*b1.y; acc[2][6]+=a.z*b1.z; acc[2][7]+=a.z*b1.w;
            acc[3][0]+=a.w*b0.x; acc[3][1]+=a.w*b0.y; acc[3][2]+=a.w*b0.z; acc[3][3]+=a.w*b0.w;
            acc[3][4]+=a.w*b1.x; acc[3][5]+=a.w*b1.y; acc[3][6]+=a.w*b1.z; acc[3][7]+=a.w*b1.w;
        }
        __syncthreads();
    }
    #pragma unroll
    for (int q = 0; q < 4; q++){
        int row = row0 + ty*4 + q;
        int bb = row / LL;
        float p = 0.f;
        #pragma unroll
        for (int j = 0; j < 8; j++){
            int n = tx*8 + j;
            p += tanhf(acc[q][j] + g_hproj[bb*HH + n]) * sdl[n];
        }
        red[ty*4+q][tx] = p;
    }
    __syncthreads();
    if (tid < 128){
        float s = 0.f;
        #pragma unroll
        for (int xk = 0; xk < 16; xk++) s += red[tid][xk];
        g_e2[row0 + tid] = s + dlb[step];
    }
}

// ---------------- softmax over L + context ----------------
__global__ void softctx_kernel(){
    __shared__ float sal[LL];
    __shared__ float sinv;
    int b = blockIdx.x, tid = threadIdx.x;  // 128 threads
    if (tid < LL) sal[tid] = g_e2[b*LL + tid];
    __syncthreads();
    if (tid == 0){
        float mx = -1e30f;
        for (int l = 0; l < LL; l++) mx = fmaxf(mx, sal[l]);
        float s = 0.f;
        for (int l = 0; l < LL; l++){ float e = __expf(sal[l]-mx); sal[l]=e; s+=e; }
        sinv = 1.f/s;
    }
    __syncthreads();
    float a = 0.f;
    #pragma unroll 5
    for (int l = 0; l < LL; l++) a += sal[l]*g_enc[(b*LL + l)*HH + tid];
    g_ctx[b*HH + tid] = a*sinv;
}

// ---------------- output head ----------------
__global__ void head_kernel(const float* __restrict__ fcw, const float* __restrict__ fcb,
                            const float* __restrict__ ow,  const float* __restrict__ ob,
                            float* __restrict__ out, int step){
    __shared__ float sh[128];
    __shared__ float sp[2];
    int b = blockIdx.x, tid = threadIdx.x;  // 64 threads
    sh[tid]      = g_hde[b*HH + tid];
    sh[tid + 64] = g_hde[b*HH + 64 + tid];
    __syncthreads();
    float s = fcb[step*64 + tid];
    const float* W = fcw + step*HH*64;
    #pragma unroll 8
    for (int k = 0; k < 128; k++) s += sh[k]*W[k*64 + tid];
    float y = tanhf(s)*ow[step*64 + tid];
    #pragma unroll
    for (int off = 16; off; off >>= 1) y += __shfl_down_sync(0xffffffffu, y, off);
    if ((tid & 31) == 0) sp[tid >> 5] = y;
    __syncthreads();
    if (tid == 0){
        float r = sp[0] + sp[1] + ob[step];
        out[b*NOUTS + step] = 1.f/(1.f + __expf(-r));
    }
}

// ---------------- launcher ----------------
extern "C" void kernel_launch(void* const* d_in, const int* in_sizes, int n_in,
                              void* d_out, int out_size){
    const float* x     = (const float*)d_in[0];
    const float* eWih  = (const float*)d_in[1];
    const float* eWhh  = (const float*)d_in[2];
    const float* ebih  = (const float*)d_in[3];
    const float* ebhh  = (const float*)d_in[4];
    const float* attw  = (const float*)d_in[5];
    const float* attb  = (const float*)d_in[6];
    const float* dWih  = (const float*)d_in[7];
    const float* dWhh  = (const float*)d_in[8];
    const float* dbih  = (const float*)d_in[9];
    const float* dbhh  = (const float*)d_in[10];
    const float* ddw   = (const float*)d_in[11];
    const float* ddb   = (const float*)d_in[12];
    const float* dlw   = (const float*)d_in[13];
    const float* dlb   = (const float*)d_in[14];
    const float* fcw   = (const float*)d_in[15];
    const float* fcb   = (const float*)d_in[16];
    const float* ow    = (const float*)d_in[17];
    const float* ob    = (const float*)d_in[18];
    float* out = (float*)d_out;

    const int ENC_SMEM = 52224 * 4;            // 208,896 B -> 1 block/SM
    const int DEC_SMEM = (7680 + 16384) * 4;   // 96,256 B
    cudaFuncSetAttribute(enc_persist_kernel, cudaFuncAttributeMaxDynamicSharedMemorySize, ENC_SMEM);
    cudaFuncSetAttribute(dec_step_kernel, cudaFuncAttributeMaxDynamicSharedMemorySize, DEC_SMEM);

    zero_kernel<<<(BB*HH + 255)/256, 256>>>();
    prep_kernel<<<(2*KDEC*256 + 255)/256, 256>>>(eWih, eWhh, ebih, ebhh, dWih, dWhh, dbih, dbhh, ddw);

    enc_persist_kernel<<<BB/BME, 512, ENC_SMEM>>>(x, attw, attb);

    for (int i = 0; i < NOUTS; i++){
        hproj_kernel<<<BB/16, 256>>>(ddb, i);
        dattn_kernel<<<(BB*LL)/128, 512>>>(ddw, dlw, dlb, i);
        softctx_kernel<<<BB, 128>>>();
        dec_step_kernel<<<dim3(2, BB/16), 256, DEC_SMEM>>>();
        head_kernel<<<BB, 64>>>(fcw, fcb, ow, ob, out, i);
    }
}

// round 17
// speedup vs baseline: 1.0924x; 1.0924x over previous
#include <cuda_runtime.h>
#include <cstdint>
#include <math.h>

#define BB 2048
#define LL 50
#define FF 64
#define HH 128
#define NOUTS 3
#define G4 512   // 4*H
#define KENC 192 // F + H
#define KDEC 384 // 2H + H
#define BME 16   // rows per encoder block

// ---------------- scratch (static device allocations only) ----------------
__device__ float g_hde[BB*HH];
__device__ float g_cde[BB*HH];
__device__ float g_enc[BB*LL*HH];
__device__ float g_ctx[BB*HH];
__device__ float g_hproj[BB*HH];
__device__ float g_e2[BB*LL];
// encoder packed weights (full width): [k][nc*4 + gate], n = gate*128 + nc
__device__ float g_WencF[KENC*G4];
__device__ float g_bencF[G4];
// decoder packed weights (halved): [half][k][nl*4 + gate], n = gate*128 + half*64 + nl
__device__ float g_WdecP[2*KDEC*256];
__device__ float g_bdecP[512];
// h-side decoder attention weight, transposed: [step][c][k]
__device__ float g_W2T[NOUTS*128*128];

__device__ __forceinline__ float sigf(float v){ return 1.f/(1.f+__expf(-v)); }

__device__ __forceinline__ void cp16(void* dst, const void* src){
    unsigned int d = (unsigned int)__cvta_generic_to_shared(dst);
    asm volatile("cp.async.ca.shared.global [%0], [%1], 16;" :: "r"(d), "l"(src));
}
__device__ __forceinline__ void cp_commit(){ asm volatile("cp.async.commit_group;"); }
__device__ __forceinline__ void cp_wait1(){ asm volatile("cp.async.wait_group 1;"); }
__device__ __forceinline__ void cp_wait0(){ asm volatile("cp.async.wait_group 0;"); }

// ---------------- init / weight prep ----------------
__global__ void zero_kernel(){
    int idx = blockIdx.x*256 + threadIdx.x;
    if (idx < BB*HH){ g_hde[idx]=0.f; g_cde[idx]=0.f; }
}

__global__ void prep_kernel(const float* __restrict__ eWih, const float* __restrict__ eWhh,
                            const float* __restrict__ ebih, const float* __restrict__ ebhh,
                            const float* __restrict__ dWih, const float* __restrict__ dWhh,
                            const float* __restrict__ dbih, const float* __restrict__ dbhh,
                            const float* __restrict__ ddw){
    int idx = blockIdx.x*256 + threadIdx.x;
    if (idx < KENC*G4){
        int k = idx >> 9, c = idx & 511;
        int nc = c >> 2, g = c & 3;
        int n = g*128 + nc;
        g_WencF[idx] = (k < FF) ? eWih[n*FF + k] : eWhh[n*HH + (k - FF)];
    }
    if (idx < 2*KDEC*256){
        int half = idx / (KDEC*256);
        int rem  = idx % (KDEC*256);
        int k = rem >> 8, r = rem & 255;
        int nl = r >> 2, g = r & 3;
        int n = g*128 + half*64 + nl;
        g_WdecP[idx] = (k < 256) ? dWih[n*256 + k] : dWhh[n*HH + (k - 256)];
    }
    if (idx < NOUTS*128*128){
        int s = idx / (128*128);
        int rem = idx % (128*128);
        int c = rem >> 7, k = rem & 127;
        g_W2T[idx] = ddw[s*256*128 + (128 + k)*128 + c];
    }
    if (idx < 512){
        int nc = idx >> 2, g = idx & 3;
        int n = g*128 + nc;
        g_bencF[idx] = ebih[n] + ebhh[n];
        int half = idx >> 8, r = idx & 255;
        int nl2 = r >> 2, g2 = r & 3;
        int n2 = g2*128 + half*64 + nl2;
        g_bdecP[idx] = dbih[n2] + dbhh[n2];
    }
}

// =======================================================================
// PERSISTENT ENCODER v3 (unchanged best): grid 128, 512 threads.
// =======================================================================
__global__ void enc_persist_kernel(const float* __restrict__ x,
                                   const float* __restrict__ aw,
                                   const float* __restrict__ ab){
    extern __shared__ float sm[];
    float* sAT = sm;             // [k][m] stride 16; k<64: xin, k>=64: h
    float* sE  = sm + 3072;      // [2][16][64]
    float* sC  = sm + 5120;      // [16][128]
    float* sAW = sm + 7168;      // aw[t]: 192x64
    float* sB  = sm + 19456;     // 2 x 32x512 weight slabs
    int tid = threadIdx.x;
    int row0 = blockIdx.x * BME;
    int tx = tid & 127, ty = tid >> 7;
    int cg = tid & 15, r1 = (tid >> 4) & 15, ks = tid >> 8;

    for (int i = tid; i < 2048; i += 512) sAT[1024 + i] = 0.f;
    for (int i = tid; i < 2048; i += 512) sC[i] = 0.f;
    float4 bg = *(const float4*)&g_bencF[tx*4];
    for (int i = tid*4; i < KENC*FF; i += 2048) cp16(sAW + i, aw + i);
    cp_commit(); cp_wait0();
    __syncthreads();

    for (int t = 0; t < LL; t++){
        for (int i = tid; i < BME*64; i += 512){
            int m = i >> 6, f = i & 63;
            sAT[f*16 + m] = x[((row0+m)*LL + t)*FF + f];
        }
        __syncthreads();

        {
            float a0=0.f, a1=0.f, a2=0.f, a3=0.f;
            int kbeg = ks*96;
            #pragma unroll 8
            for (int k = kbeg; k < kbeg+96; k++){
                float4 b = *(const float4*)&sAW[k*64 + cg*4];
                float a = sAT[k*16 + r1];
                a0 += a*b.x; a1 += a*b.y; a2 += a*b.z; a3 += a*b.w;
            }
            *(float4*)&sE[(ks*16 + r1)*64 + cg*4] = make_float4(a0, a1, a2, a3);
        }
        __syncthreads();

        {
            int w = tid >> 5, lane = tid & 31;
            float b0 = __ldg(&ab[t*FF + lane]);
            float b1 = __ldg(&ab[t*FF + 32 + lane]);
            float v0 = tanhf(sE[w*64 + lane]        + sE[(16+w)*64 + lane]        + b0);
            float v1 = tanhf(sE[w*64 + lane + 32]   + sE[(16+w)*64 + lane + 32]   + b1);
            float mx = fmaxf(v0, v1);
            #pragma unroll
            for (int off = 16; off; off >>= 1) mx = fmaxf(mx, __shfl_xor_sync(0xffffffffu, mx, off));
            float e0 = __expf(v0 - mx), e1 = __expf(v1 - mx);
            float s = e0 + e1;
            #pragma unroll
            for (int off = 16; off; off >>= 1) s += __shfl_xor_sync(0xffffffffu, s, off);
            float inv = 1.f/s;
            sAT[lane*16 + w]      *= e0*inv;
            sAT[(lane+32)*16 + w] *= e1*inv;
        }
        __syncthreads();

        if (t+1 < LL){
            const float* awn = aw + (size_t)(t+1)*KENC*FF;
            for (int i = tid*4; i < KENC*FF; i += 2048) cp16(sAW + i, awn + i);
        }
        for (int i = tid*4; i < 16384; i += 2048) cp16(sB + i, g_WencF + i);
        cp_commit();
        float acc[4][4] = {};
        #pragma unroll 1
        for (int s = 0; s < 6; s++){
            if (s < 5){
                float* dst = sB + ((s+1)&1)*16384;
                const float* src = g_WencF + (s+1)*16384;
                for (int i = tid*4; i < 16384; i += 2048) cp16(dst + i, src + i);
                cp_commit(); cp_wait1();
            } else cp_wait0();
            __syncthreads();
            const float* Bf = sB + (s&1)*16384;
            #pragma unroll
            for (int kk = 0; kk < 32; kk++){
                int k = s*32 + kk;
                float4 a = *(const float4*)&sAT[k*16 + ty*4];
                float4 b = *(const float4*)&Bf[kk*512 + tx*4];
                acc[0][0]+=a.x*b.x; acc[0][1]+=a.x*b.y; acc[0][2]+=a.x*b.z; acc[0][3]+=a.x*b.w;
                acc[1][0]+=a.y*b.x; acc[1][1]+=a.y*b.y; acc[1][2]+=a.y*b.z; acc[1][3]+=a.y*b.w;
                acc[2][0]+=a.z*b.x; acc[2][1]+=a.z*b.y; acc[2][2]+=a.z*b.z; acc[2][3]+=a.z*b.w;
                acc[3][0]+=a.w*b.x; acc[3][1]+=a.w*b.y; acc[3][2]+=a.w*b.z; acc[3][3]+=a.w*b.w;
            }
            __syncthreads();
        }
        #pragma unroll
        for (int q = 0; q < 4; q++){
            int ml = ty*4 + q;
            float ig = sigf (acc[q][0] + bg.x);
            float fg = sigf (acc[q][1] + bg.y);
            float gg = tanhf(acc[q][2] + bg.z);
            float og = sigf (acc[q][3] + bg.w);
            float cn = fg*sC[ml*128 + tx] + ig*gg;
            sC[ml*128 + tx] = cn;
            float h = og*tanhf(cn);
            sAT[(64+tx)*16 + ml] = h;
            g_enc[((row0+ml)*LL + t)*HH + tx] = h;
        }
    }
}

// =======================================================================
// FUSED DECODER LSTM STEP: grid (2, 128), BK=16 cp.async pipeline, K=384
// (reverted to the 1595us configuration)
// =======================================================================
__global__ void dec_step_kernel(){
    extern __shared__ float sm[];
    float* sAT = sm;                  // 384*20 = 7680
    float* sB  = sm + 7680;           // 2 x 16x256 = 8192
    int tid = threadIdx.x;
    int half = blockIdx.x;
    int row0 = blockIdx.y * 16;

    for (int i = tid; i < 16*128; i += 256){
        int m = i >> 7, k = i & 127;
        float ctx = g_ctx[(row0+m)*HH + k];
        float h   = g_hde[(row0+m)*HH + k];
        sAT[k*20 + m]       = ctx;
        sAT[(128+k)*20 + m] = h;
        sAT[(256+k)*20 + m] = h;
    }
    int tx = tid & 63, ty = tid >> 6;
    const float* Wp = g_WdecP + half*(KDEC*256);
    {
        #pragma unroll
        for (int i = tid*4; i < 4096; i += 1024) cp16(sB + i, Wp + i);
        cp_commit();
    }
    __syncthreads();
    float acc[4][4] = {};
    #pragma unroll 1
    for (int s = 0; s < 24; s++){
        if (s < 23){
            float* dst = sB + ((s+1)&1)*4096;
            const float* src = Wp + (s+1)*4096;
            #pragma unroll
            for (int i = tid*4; i < 4096; i += 1024) cp16(dst + i, src + i);
            cp_commit();
            cp_wait1();
        } else {
            cp_wait0();
        }
        __syncthreads();
        const float* Bf = sB + (s&1)*4096;
        #pragma unroll
        for (int kk = 0; kk < 16; kk++){
            int k = s*16 + kk;
            float4 a = *(const float4*)&sAT[k*20 + ty*4];
            float4 b = *(const float4*)&Bf[kk*256 + tx*4];
            acc[0][0]+=a.x*b.x; acc[0][1]+=a.x*b.y; acc[0][2]+=a.x*b.z; acc[0][3]+=a.x*b.w;
            acc[1][0]+=a.y*b.x; acc[1][1]+=a.y*b.y; acc[1][2]+=a.y*b.z; acc[1][3]+=a.y*b.w;
            acc[2][0]+=a.z*b.x; acc[2][1]+=a.z*b.y; acc[2][2]+=a.z*b.z; acc[2][3]+=a.z*b.w;
            acc[3][0]+=a.w*b.x; acc[3][1]+=a.w*b.y; acc[3][2]+=a.w*b.z; acc[3][3]+=a.w*b.w;
        }
        __syncthreads();
    }
    {
        int n = half*64 + tx;
        const float* bP = g_bdecP + half*256;
        float b0 = bP[tx*4+0], b1 = bP[tx*4+1], b2 = bP[tx*4+2], b3 = bP[tx*4+3];
        #pragma unroll
        for (int q = 0; q < 4; q++){
            int row = row0 + ty*4 + q;
            float ig = sigf (acc[q][0] + b0);
            float fg = sigf (acc[q][1] + b1);
            float gg = tanhf(acc[q][2] + b2);
            float og = sigf (acc[q][3] + b3);
            float cn = fg*g_cde[row*HH + n] + ig*gg;
            g_cde[row*HH + n] = cn;
            g_hde[row*HH + n] = og*tanhf(cn);
        }
    }
}

// ---------------- hproj v3 (kept: measured 21.8 -> 16.0 us) ----------------
__global__ void hproj_kernel(const float* __restrict__ ddb, int step){
    __shared__ float shT[128*16];   // [k][m] stride 16
    int tid = threadIdx.x;
    int row0 = blockIdx.x * 16;
    for (int i = tid; i < 2048; i += 256){
        int m = i >> 7, k = i & 127;
        shT[k*16 + m] = g_hde[(row0+m)*HH + k];
    }
    __syncthreads();
    int c = tid & 127, rg = tid >> 7;    // rows rg*8..rg*8+7
    const float* Wt = g_W2T + step*128*128 + c*128;
    float acc[8] = {};
    #pragma unroll 8
    for (int k = 0; k < 128; k += 4){
        float4 b = *(const float4*)&Wt[k];
        #pragma unroll
        for (int j = 0; j < 4; j++){
            float bj = j==0?b.x : j==1?b.y : j==2?b.z : b.w;
            float4 h0 = *(const float4*)&shT[(k+j)*16 + rg*8];
            float4 h1 = *(const float4*)&shT[(k+j)*16 + rg*8 + 4];
            acc[0]+=h0.x*bj; acc[1]+=h0.y*bj; acc[2]+=h0.z*bj; acc[3]+=h0.w*bj;
            acc[4]+=h1.x*bj; acc[5]+=h1.y*bj; acc[6]+=h1.z*bj; acc[7]+=h1.w*bj;
        }
    }
    float bias = ddb[step*128 + c];
    #pragma unroll
    for (int r = 0; r < 8; r++)
        g_hproj[(row0 + rg*8 + r)*HH + c] = acc[r] + bias;
}

// ---------------- decoder temporal attention, 128x128 tile, 256 thr, 8x8 ----
// (reverted to the 1595us configuration)
__global__ void dattn_kernel(const float* __restrict__ ddw, const float* __restrict__ dlw,
                             const float* __restrict__ dlb, int step){
    __shared__ float sA[16*136];
    __shared__ float sB[16][128];
    __shared__ float sdl[128];
    __shared__ float red[128][17];
    int tid = threadIdx.x, tx = tid & 15, ty = tid >> 4;
    int row0 = blockIdx.x * 128;
    if (tid < 128) sdl[tid] = dlw[step*128 + tid];
    const float* W = ddw + step*256*128;
    float acc[8][8] = {};
    for (int k0 = 0; k0 < 128; k0 += 16){
        for (int i = tid; i < 128*16; i += 256){
            int m = i >> 4, k = i & 15;
            sA[k*136 + m] = g_enc[(row0+m)*HH + k0 + k];
        }
        for (int i = tid; i < 16*128; i += 256){
            int k = i >> 7, n = i & 127;
            sB[k][n] = W[(k0+k)*128 + n];
        }
        __syncthreads();
        #pragma unroll
        for (int kk = 0; kk < 16; kk++){
            float4 a0 = *(const float4*)&sA[kk*136 + ty*8];
            float4 a1 = *(const float4*)&sA[kk*136 + ty*8 + 4];
            float a[8] = {a0.x,a0.y,a0.z,a0.w,a1.x,a1.y,a1.z,a1.w};
            float4 b0 = *(const float4*)&sB[kk][tx*8];
            float4 b1 = *(const float4*)&sB[kk][tx*8+4];
            #pragma unroll
            for (int q = 0; q < 8; q++){
                acc[q][0]+=a[q]*b0.x; acc[q][1]+=a[q]*b0.y; acc[q][2]+=a[q]*b0.z; acc[q][3]+=a[q]*b0.w;
                acc[q][4]+=a[q]*b1.x; acc[q][5]+=a[q]*b1.y; acc[q][6]+=a[q]*b1.z; acc[q][7]+=a[q]*b1.w;
            }
        }
        __syncthreads();
    }
    #pragma unroll
    for (int q = 0; q < 8; q++){
        int row = row0 + ty*8 + q;
        int bb = row / LL;
        float p = 0.f;
        #pragma unroll
        for (int j = 0; j < 8; j++){
            int n = tx*8 + j;
            p += tanhf(acc[q][j] + g_hproj[bb*HH + n]) * sdl[n];
        }
        red[ty*8+q][tx] = p;
    }
    __syncthreads();
    if (tid < 128){
        float s = 0.f;
        #pragma unroll
        for (int xk = 0; xk < 16; xk++) s += red[tid][xk];
        g_e2[row0 + tid] = s + dlb[step];
    }
}

// ---------------- softmax over L + context ----------------
__global__ void softctx_kernel(){
    __shared__ float sal[LL];
    __shared__ float sinv;
    int b = blockIdx.x, tid = threadIdx.x;  // 128 threads
    if (tid < LL) sal[tid] = g_e2[b*LL + tid];
    __syncthreads();
    if (tid == 0){
        float mx = -1e30f;
        for (int l = 0; l < LL; l++) mx = fmaxf(mx, sal[l]);
        float s = 0.f;
        for (int l = 0; l < LL; l++){ float e = __expf(sal[l]-mx); sal[l]=e; s+=e; }
        sinv = 1.f/s;
    }
    __syncthreads();
    float a = 0.f;
    #pragma unroll 5
    for (int l = 0; l < LL; l++) a += sal[l]*g_enc[(b*LL + l)*HH + tid];
    g_ctx[b*HH + tid] = a*sinv;
}

// ---------------- output head ----------------
__global__ void head_kernel(const float* __restrict__ fcw, const float* __restrict__ fcb,
                            const float* __restrict__ ow,  const float* __restrict__ ob,
                            float* __restrict__ out, int step){
    __shared__ float sh[128];
    __shared__ float sp[2];
    int b = blockIdx.x, tid = threadIdx.x;  // 64 threads
    sh[tid]      = g_hde[b*HH + tid];
    sh[tid + 64] = g_hde[b*HH + 64 + tid];
    __syncthreads();
    float s = fcb[step*64 + tid];
    const float* W = fcw + step*HH*64;
    #pragma unroll 8
    for (int k = 0; k < 128; k++) s += sh[k]*W[k*64 + tid];
    float y = tanhf(s)*ow[step*64 + tid];
    #pragma unroll
    for (int off = 16; off; off >>= 1) y += __shfl_down_sync(0xffffffffu, y, off);
    if ((tid & 31) == 0) sp[tid >> 5] = y;
    __syncthreads();
    if (tid == 0){
        float r = sp[0] + sp[1] + ob[step];
        out[b*NOUTS + step] = 1.f/(1.f + __expf(-r));
    }
}

// ---------------- launcher ----------------
extern "C" void kernel_launch(void* const* d_in, const int* in_sizes, int n_in,
                              void* d_out, int out_size){
    const float* x     = (const float*)d_in[0];
    const float* eWih  = (const float*)d_in[1];
    const float* eWhh  = (const float*)d_in[2];
    const float* ebih  = (const float*)d_in[3];
    const float* ebhh  = (const float*)d_in[4];
    const float* attw  = (const float*)d_in[5];
    const float* attb  = (const float*)d_in[6];
    const float* dWih  = (const float*)d_in[7];
    const float* dWhh  = (const float*)d_in[8];
    const float* dbih  = (const float*)d_in[9];
    const float* dbhh  = (const float*)d_in[10];
    const float* ddw   = (const float*)d_in[11];
    const float* ddb   = (const float*)d_in[12];
    const float* dlw   = (const float*)d_in[13];
    const float* dlb   = (const float*)d_in[14];
    const float* fcw   = (const float*)d_in[15];
    const float* fcb   = (const float*)d_in[16];
    const float* ow    = (const float*)d_in[17];
    const float* ob    = (const float*)d_in[18];
    float* out = (float*)d_out;

    const int ENC_SMEM = 52224 * 4;          // 208,896 B -> 1 block/SM
    const int DEC_SMEM = (7680 + 8192) * 4;  // 63,488 B
    cudaFuncSetAttribute(enc_persist_kernel, cudaFuncAttributeMaxDynamicSharedMemorySize, ENC_SMEM);
    cudaFuncSetAttribute(dec_step_kernel, cudaFuncAttributeMaxDynamicSharedMemorySize, DEC_SMEM);

    zero_kernel<<<(BB*HH + 255)/256, 256>>>();
    prep_kernel<<<(2*KDEC*256 + 255)/256, 256>>>(eWih, eWhh, ebih, ebhh, dWih, dWhh, dbih, dbhh, ddw);

    enc_persist_kernel<<<BB/BME, 512, ENC_SMEM>>>(x, attw, attb);

    for (int i = 0; i < NOUTS; i++){
        hproj_kernel<<<BB/16, 256>>>(ddb, i);
        dattn_kernel<<<(BB*LL)/128, 256>>>(ddw, dlw, dlb, i);
        softctx_kernel<<<BB, 128>>>();
        dec_step_kernel<<<dim3(2, BB/16), 256, DEC_SMEM>>>();
        head_kernel<<<BB, 64>>>(fcw, fcb, ow, ob, out, i);
    }
}